// round 1
// baseline (speedup 1.0000x reference)
#include <cuda_runtime.h>

// sLSTM: B=256, T=512, D=8, H=120, L=4, NH=8, HD=15
// Strategy: 128 CTAs x 128 threads; each CTA owns 2 batch elements through all
// 4 layers (batches independent until final BN). Per batch, 60 threads each
// compute a PAIR of h outputs (j, j+60) using packed fp32x2 FMA (FFMA2),
// doubling fp32 MAC throughput. h broadcast via shared (double buffered, one
// __syncthreads per step). Down-projection done in 64-step chunks with hs kept
// in shared. Final batchnorm+fc+sigmoid in a tiny second kernel.

#define B_ 256
#define T_ 512
#define D_ 8
#define H_ 120
#define L_ 4
#define NPAIR 60
#define HS_STRIDE 72   // padded row stride (float2) to mitigate bank conflicts

typedef unsigned long long ull;

__device__ float g_last[B_ * D_];

__device__ __forceinline__ ull f2pack(float x, float y) {
    ull r; asm("mov.b64 %0, {%1, %2};" : "=l"(r) : "f"(x), "f"(y)); return r;
}
__device__ __forceinline__ void f2unpack(ull v, float& x, float& y) {
    asm("mov.b64 {%0, %1}, %2;" : "=f"(x), "=f"(y) : "l"(v));
}
__device__ __forceinline__ float f2lo(ull v) {
    float x, y; f2unpack(v, x, y); return x;
}
__device__ __forceinline__ ull f2fma(ull a, ull b, ull c) {
    ull d; asm("fma.rn.f32x2 %0, %1, %2, %3;" : "=l"(d) : "l"(a), "l"(b), "l"(c));
    return d;
}

// one sLSTM cell update for a single scalar lane
__device__ __forceinline__ float cellf(float it, float ft, float zt, float ot,
                                       float& c, float& nn, float& m) {
    float mn = fmaxf(ft + m, it);
    float ip = __expf(it - mn);
    float fp = __expf(ft + m - mn);
    float az = fabsf(zt);
    float ez = __expf(-2.f * az);
    float z  = __fdividef(1.f - ez, 1.f + ez);
    z = copysignf(z, zt);
    c  = fp * c  + ip * z;
    nn = fp * nn + ip;
    m  = mn;
    float eo = __expf(-ot);              // sigmoid folded into one division:
    return __fdividef(c, nn * (1.f + eo)); // h = o * c / n = c / (n*(1+e^-ot))
}

// shared layout (in ull units):
//   x2  [2][512*8]   = 8192   (input/residual stream, value duplicated (v,v))
//   hs  [2][64*72]   = 9216   (chunk h history, paired (h_j, h_{j+60}))
//   h2  [2][2][64]   = 256    (double-buffered current h, paired)
//   wp2 [8*60]       = 480    (paired Wp)
//   bps [8 floats]
#define SM_X2  0
#define SM_HS  8192
#define SM_H2  (8192 + 9216)
#define SM_WP  (SM_H2 + 256)
#define SM_TOT (SM_WP + 480)
#define SMEM_BYTES (SM_TOT * 8 + 32)

__global__ void __launch_bounds__(128, 1) slstm_kernel(
    const float* __restrict__ X,
    const float* __restrict__ Wi, const float* __restrict__ Wf,
    const float* __restrict__ Wz, const float* __restrict__ Wo,
    const float* __restrict__ Ri, const float* __restrict__ Rf,
    const float* __restrict__ Rz, const float* __restrict__ Ro,
    const float* __restrict__ bi, const float* __restrict__ bf,
    const float* __restrict__ bz, const float* __restrict__ bo,
    const float* __restrict__ Wp, const float* __restrict__ bp)
{
    extern __shared__ ull sm[];
    ull* x2   = sm + SM_X2;
    ull* hsb  = sm + SM_HS;
    ull* h2   = sm + SM_H2;
    ull* wp2  = sm + SM_WP;
    float* bps = (float*)(sm + SM_TOT);

    const int tid = threadIdx.x;
    const int bb  = tid >> 6;        // which of 2 batches in this CTA
    const int s   = tid & 63;        // pair slot (active if < 60)
    const int b0  = blockIdx.x * 2;
    const bool act = (s < NPAIR);
    const int n = s / 15;            // head block (pairs with n+4)
    const int e = s - n * 15;

    // load input x for both batches, duplicated (v,v)
    for (int idx = tid; idx < 2 * T_ * D_; idx += 128) {
        int bbi = idx >> 12;
        int i   = idx & 4095;
        float v = X[(b0 + bbi) * (T_ * D_) + i];
        x2[bbi * 4096 + i] = f2pack(v, v);
    }
    __syncthreads();

    #pragma unroll 1
    for (int l = 0; l < L_; l++) {
        // ---- per-thread packed weights into registers ----
        ull rIv[15], rFv[15], rZv[15], rOv[15];
        ull wIv[8],  wFv[8],  wZv[8],  wOv[8];
        ull bIv = 0, bFv = 0, bZv = 0, bOv = 0;
        if (act) {
            const float* wi = Wi + l * H_ * D_;
            const float* wf = Wf + l * H_ * D_;
            const float* wz = Wz + l * H_ * D_;
            const float* wo = Wo + l * H_ * D_;
            #pragma unroll
            for (int d = 0; d < 8; d++) {
                wIv[d] = f2pack(wi[s * 8 + d], wi[(s + 60) * 8 + d]);
                wFv[d] = f2pack(wf[s * 8 + d], wf[(s + 60) * 8 + d]);
                wZv[d] = f2pack(wz[s * 8 + d], wz[(s + 60) * 8 + d]);
                wOv[d] = f2pack(wo[s * 8 + d], wo[(s + 60) * 8 + d]);
            }
            const float* ri = Ri + l * 8 * 225;
            const float* rf = Rf + l * 8 * 225;
            const float* rz = Rz + l * 8 * 225;
            const float* ro = Ro + l * 8 * 225;
            #pragma unroll
            for (int d = 0; d < 15; d++) {
                int i0 = n * 225 + d * 15 + e;
                int i1 = (n + 4) * 225 + d * 15 + e;
                rIv[d] = f2pack(ri[i0], ri[i1]);
                rFv[d] = f2pack(rf[i0], rf[i1]);
                rZv[d] = f2pack(rz[i0], rz[i1]);
                rOv[d] = f2pack(ro[i0], ro[i1]);
            }
            bIv = f2pack(bi[l * H_ + s], bi[l * H_ + s + 60]);
            bFv = f2pack(bf[l * H_ + s], bf[l * H_ + s + 60]);
            bZv = f2pack(bz[l * H_ + s], bz[l * H_ + s + 60]);
            bOv = f2pack(bo[l * H_ + s], bo[l * H_ + s + 60]);
        }
        // paired Wp + bp into shared
        for (int idx = tid; idx < 8 * NPAIR; idx += 128) {
            int d = idx / NPAIR, p = idx - d * NPAIR;
            const float* wp = Wp + l * D_ * H_;
            wp2[idx] = f2pack(wp[d * H_ + p], wp[d * H_ + p + 60]);
        }
        if (tid < 8) bps[tid] = bp[l * D_ + tid];
        // zero h double buffers
        for (int idx = tid; idx < 256; idx += 128) h2[idx] = 0ull;
        __syncthreads();

        float c0 = 0.f, c1 = 0.f, n0 = 0.f, n1 = 0.f, m0 = 0.f, m1 = 0.f;
        int buf = 0;

        #pragma unroll 1
        for (int ch = 0; ch < 8; ch++) {
            const int tbase = ch * 64;
            // ---- scan 64 steps ----
            #pragma unroll 1
            for (int tt = 0; tt < 64; tt++) {
                if (act) {
                    ull aI = bIv, aF = bFv, aZ = bZv, aO = bOv;
                    const ull* __restrict__ xr = x2 + bb * 4096 + (tbase + tt) * 8;
                    #pragma unroll
                    for (int d = 0; d < 8; d++) {
                        ull xv = xr[d];
                        aI = f2fma(xv, wIv[d], aI);
                        aF = f2fma(xv, wFv[d], aF);
                        aZ = f2fma(xv, wZv[d], aZ);
                        aO = f2fma(xv, wOv[d], aO);
                    }
                    const ull* __restrict__ hr = h2 + bb * 128 + buf * 64 + n * 16;
                    #pragma unroll
                    for (int d = 0; d < 15; d++) {
                        ull hv = hr[d];
                        aI = f2fma(hv, rIv[d], aI);
                        aF = f2fma(hv, rFv[d], aF);
                        aZ = f2fma(hv, rZv[d], aZ);
                        aO = f2fma(hv, rOv[d], aO);
                    }
                    float itx, ity, ftx, fty, ztx, zty, otx, oty;
                    f2unpack(aI, itx, ity); f2unpack(aF, ftx, fty);
                    f2unpack(aZ, ztx, zty); f2unpack(aO, otx, oty);
                    float hx = cellf(itx, ftx, ztx, otx, c0, n0, m0);
                    float hy = cellf(ity, fty, zty, oty, c1, n1, m1);
                    ull hv2 = f2pack(hx, hy);
                    h2[bb * 128 + (buf ^ 1) * 64 + n * 16 + e] = hv2;
                    hsb[bb * (64 * HS_STRIDE) + tt * HS_STRIDE + s] = hv2;
                }
                __syncthreads();
                buf ^= 1;
            }
            // ---- projection: xnext[t] = x[t] + hs[t] @ Wp^T + bp for this chunk ----
            {
                const int tl = s;  // all 128 threads: (bb, tl) covers 2x64 tasks
                ull acc[8];
                #pragma unroll
                for (int d = 0; d < 8; d++) acc[d] = 0ull;
                const ull* __restrict__ hsr = hsb + bb * (64 * HS_STRIDE) + tl * HS_STRIDE;
                #pragma unroll 6
                for (int p = 0; p < NPAIR; p++) {
                    ull hv = hsr[p];
                    #pragma unroll
                    for (int d = 0; d < 8; d++)
                        acc[d] = f2fma(hv, wp2[d * NPAIR + p], acc[d]);
                }
                int t = tbase + tl;
                ull* xr = x2 + bb * 4096 + t * 8;
                #pragma unroll
                for (int d = 0; d < 8; d++) {
                    float ax, ay; f2unpack(acc[d], ax, ay);
                    float nv = f2lo(xr[d]) + ax + ay + bps[d];
                    xr[d] = f2pack(nv, nv);
                }
            }
            __syncthreads();
        }
    }

    // stash last timestep (layer-stack output) for the finalize kernel
    if (tid < 16) {
        int bbi = tid >> 3, d = tid & 7;
        g_last[(b0 + bbi) * D_ + d] = f2lo(x2[bbi * 4096 + 511 * 8 + d]);
    }
}

__global__ void finalize_kernel(const float* __restrict__ gamma,
                                const float* __restrict__ beta,
                                const float* __restrict__ wfc,
                                const float* __restrict__ bfc,
                                float* __restrict__ out)
{
    __shared__ float red[8][8];
    __shared__ float smu[8], svar[8];
    int b = threadIdx.x;
    int lane = b & 31, w = b >> 5;
    float v[8];
    #pragma unroll
    for (int d = 0; d < 8; d++) v[d] = g_last[b * 8 + d];

    // mean over batch per feature
    #pragma unroll
    for (int d = 0; d < 8; d++) {
        float sv = v[d];
        #pragma unroll
        for (int o = 16; o > 0; o >>= 1) sv += __shfl_xor_sync(0xffffffffu, sv, o);
        if (lane == 0) red[d][w] = sv;
    }
    __syncthreads();
    if (b < 8) {
        float sv = 0.f;
        #pragma unroll
        for (int k = 0; k < 8; k++) sv += red[b][k];
        smu[b] = sv * (1.f / 256.f);
    }
    __syncthreads();
    float mu[8];
    #pragma unroll
    for (int d = 0; d < 8; d++) mu[d] = smu[d];
    __syncthreads();

    // variance
    #pragma unroll
    for (int d = 0; d < 8; d++) {
        float dv = v[d] - mu[d];
        float sv = dv * dv;
        #pragma unroll
        for (int o = 16; o > 0; o >>= 1) sv += __shfl_xor_sync(0xffffffffu, sv, o);
        if (lane == 0) red[d][w] = sv;
    }
    __syncthreads();
    if (b < 8) {
        float sv = 0.f;
        #pragma unroll
        for (int k = 0; k < 8; k++) sv += red[b][k];
        svar[b] = sv * (1.f / 256.f);
    }
    __syncthreads();

    float acc = bfc[0];
    #pragma unroll
    for (int d = 0; d < 8; d++) {
        float bn = (v[d] - mu[d]) * rsqrtf(svar[d] + 1e-5f) * gamma[d] + beta[d];
        acc = fmaf(bn, wfc[d], acc);
    }
    out[b] = 1.f / (1.f + expf(-acc));
}

extern "C" void kernel_launch(void* const* d_in, const int* in_sizes, int n_in,
                              void* d_out, int out_size) {
    const float* X    = (const float*)d_in[0];
    const float* Wi   = (const float*)d_in[1];
    const float* Wf   = (const float*)d_in[2];
    const float* Wz   = (const float*)d_in[3];
    const float* Wo   = (const float*)d_in[4];
    const float* Ri   = (const float*)d_in[5];
    const float* Rf   = (const float*)d_in[6];
    const float* Rz   = (const float*)d_in[7];
    const float* Ro   = (const float*)d_in[8];
    const float* bi   = (const float*)d_in[9];
    const float* bf   = (const float*)d_in[10];
    const float* bz   = (const float*)d_in[11];
    const float* bo   = (const float*)d_in[12];
    const float* Wp   = (const float*)d_in[13];
    const float* bp   = (const float*)d_in[14];
    const float* gam  = (const float*)d_in[15];
    const float* bet  = (const float*)d_in[16];
    const float* Wfc  = (const float*)d_in[17];
    const float* bfc  = (const float*)d_in[18];

    cudaFuncSetAttribute(slstm_kernel,
                         cudaFuncAttributeMaxDynamicSharedMemorySize, SMEM_BYTES);
    slstm_kernel<<<128, 128, SMEM_BYTES>>>(X, Wi, Wf, Wz, Wo, Ri, Rf, Rz, Ro,
                                           bi, bf, bz, bo, Wp, bp);
    finalize_kernel<<<1, 256>>>(gam, bet, Wfc, bfc, (float*)d_out);
}

// round 2
// speedup vs baseline: 1.0119x; 1.0119x over previous
#include <cuda_runtime.h>

// sLSTM: B=256, T=512, D=8, H=120, L=4, NH=8, HD=15
// R is block-diagonal per head => recurrence is WARP-PRIVATE:
//   warp k owns head blocks (k, k+4) as packed f32x2 pairs across 15 lanes,
//   for TWO batches (lanes 0-14 = batch0, lanes 16-30 = batch1).
//   h exchange via shfl.sync — NO per-step barrier, NO per-step shared h.
// CTA = 128 threads = 4 warps = 2 batches; grid = 128 CTAs (1 wave).
// Down-projection every 64-step chunk (hs kept in shared), then residual
// write-back into the x stream. Final batchnorm+fc+sigmoid in a tiny kernel.

#define B_ 256
#define T_ 512
#define D_ 8
#define H_ 120
#define L_ 4
#define NPAIR 60
#define ST 61   // odd hs row stride (ull) -> low bank conflict in projection

typedef unsigned long long ull;

__device__ float g_last[B_ * D_];

__device__ __forceinline__ ull f2pack(float x, float y) {
    ull r; asm("mov.b64 %0, {%1, %2};" : "=l"(r) : "f"(x), "f"(y)); return r;
}
__device__ __forceinline__ void f2unpack(ull v, float& x, float& y) {
    asm("mov.b64 {%0, %1}, %2;" : "=f"(x), "=f"(y) : "l"(v));
}
__device__ __forceinline__ float f2lo(ull v) {
    float x, y; f2unpack(v, x, y); return x;
}
__device__ __forceinline__ ull f2fma(ull a, ull b, ull c) {
    ull d; asm("fma.rn.f32x2 %0, %1, %2, %3;" : "=l"(d) : "l"(a), "l"(b), "l"(c));
    return d;
}
__device__ __forceinline__ float tanh_ap(float x) {
    float r; asm("tanh.approx.f32 %0, %1;" : "=f"(r) : "f"(x)); return r;
}
__device__ __forceinline__ float rcp_ap(float x) {
    float r; asm("rcp.approx.f32 %0, %1;" : "=f"(r) : "f"(x)); return r;
}

// one sLSTM cell update for a single scalar lane (HW tanh for z and o)
__device__ __forceinline__ float cellf(float it, float ft, float zt, float ot,
                                       float& c, float& nn, float& m) {
    float mn = fmaxf(ft + m, it);
    float ip = __expf(it - mn);
    float fp = __expf(ft + m - mn);
    float z  = tanh_ap(zt);
    c  = fp * c  + ip * z;
    nn = fp * nn + ip;
    m  = mn;
    float o = fmaf(tanh_ap(0.5f * ot), 0.5f, 0.5f);   // sigmoid via tanh
    return o * c * rcp_ap(nn);
}

// shared layout (ull units):
//   x2  [2][512*8] = 8192  (residual/x stream, duplicated (v,v))
//   hsb [2][64*ST] = 7808  (chunk h history, paired (h_j, h_{j+60}))
//   wp2 [8*60]     = 480
//   bps [8 floats] = 4
#define SM_X2 0
#define SM_HS 8192
#define SM_WP (8192 + 7808)
#define SM_BP (SM_WP + 480)
#define SM_TOT (SM_BP + 4)
#define SMEM_BYTES (SM_TOT * 8 + 16)

__global__ void __launch_bounds__(128, 1) slstm_kernel(
    const float* __restrict__ X,
    const float* __restrict__ Wi, const float* __restrict__ Wf,
    const float* __restrict__ Wz, const float* __restrict__ Wo,
    const float* __restrict__ Ri, const float* __restrict__ Rf,
    const float* __restrict__ Rz, const float* __restrict__ Ro,
    const float* __restrict__ bi, const float* __restrict__ bf,
    const float* __restrict__ bz, const float* __restrict__ bo,
    const float* __restrict__ Wp, const float* __restrict__ bp)
{
    extern __shared__ ull sm[];
    ull* x2  = sm + SM_X2;
    ull* hsb = sm + SM_HS;
    ull* wp2 = sm + SM_WP;
    float* bps = (float*)(sm + SM_BP);

    const int tid  = threadIdx.x;
    const int lane = tid & 31;
    const int k    = tid >> 5;            // warp id == head block k (pairs k+4)
    const int half = (lane >> 4) & 1;     // batch within CTA
    const int e    = lane & 15;
    const bool act = (e < 15);
    const int b0   = blockIdx.x * 2;
    const int srcbase = lane & 16;        // shfl base lane for this batch half
    const int slot = k * 15 + e;          // pair slot 0..59 (pairs with +60)

    // load input x for both batches, duplicated (v,v)
    for (int idx = tid; idx < 2 * T_ * D_; idx += 128) {
        int bbi = idx >> 12;
        int i   = idx & 4095;
        float v = X[(b0 + bbi) * (T_ * D_) + i];
        x2[bbi * 4096 + i] = f2pack(v, v);
    }

    #pragma unroll 1
    for (int l = 0; l < L_; l++) {
        // ---- per-thread packed weights into registers ----
        ull rIv[15], rFv[15], rZv[15], rOv[15];
        ull wIv[8],  wFv[8],  wZv[8],  wOv[8];
        ull bIv = 0, bFv = 0, bZv = 0, bOv = 0;
        if (act) {
            const int j0 = slot, j1 = slot + 60;
            const float* wi = Wi + l * H_ * D_;
            const float* wf = Wf + l * H_ * D_;
            const float* wz = Wz + l * H_ * D_;
            const float* wo = Wo + l * H_ * D_;
            #pragma unroll
            for (int d = 0; d < 8; d++) {
                wIv[d] = f2pack(wi[j0 * 8 + d], wi[j1 * 8 + d]);
                wFv[d] = f2pack(wf[j0 * 8 + d], wf[j1 * 8 + d]);
                wZv[d] = f2pack(wz[j0 * 8 + d], wz[j1 * 8 + d]);
                wOv[d] = f2pack(wo[j0 * 8 + d], wo[j1 * 8 + d]);
            }
            const float* ri = Ri + l * 8 * 225;
            const float* rf = Rf + l * 8 * 225;
            const float* rz = Rz + l * 8 * 225;
            const float* ro = Ro + l * 8 * 225;
            #pragma unroll
            for (int d = 0; d < 15; d++) {
                int i0 = k * 225 + d * 15 + e;
                int i1 = (k + 4) * 225 + d * 15 + e;
                rIv[d] = f2pack(ri[i0], ri[i1]);
                rFv[d] = f2pack(rf[i0], rf[i1]);
                rZv[d] = f2pack(rz[i0], rz[i1]);
                rOv[d] = f2pack(ro[i0], ro[i1]);
            }
            bIv = f2pack(bi[l * H_ + j0], bi[l * H_ + j1]);
            bFv = f2pack(bf[l * H_ + j0], bf[l * H_ + j1]);
            bZv = f2pack(bz[l * H_ + j0], bz[l * H_ + j1]);
            bOv = f2pack(bo[l * H_ + j0], bo[l * H_ + j1]);
        } else {
            #pragma unroll
            for (int d = 0; d < 15; d++) { rIv[d]=0; rFv[d]=0; rZv[d]=0; rOv[d]=0; }
            #pragma unroll
            for (int d = 0; d < 8; d++)  { wIv[d]=0; wFv[d]=0; wZv[d]=0; wOv[d]=0; }
        }
        // paired Wp + bp into shared
        for (int idx = tid; idx < 8 * NPAIR; idx += 128) {
            int d = idx / NPAIR, p = idx - d * NPAIR;
            const float* wp = Wp + l * D_ * H_;
            wp2[idx] = f2pack(wp[d * H_ + p], wp[d * H_ + p + 60]);
        }
        if (tid < 8) bps[tid] = bp[l * D_ + tid];
        __syncthreads();

        float c0 = 0.f, c1 = 0.f, n0 = 0.f, n1 = 0.f, m0 = 0.f, m1 = 0.f;
        float h0 = 0.f, h1 = 0.f;

        #pragma unroll 1
        for (int ch = 0; ch < 8; ch++) {
            const int tbase = ch * 64;
            // ---- scan 64 steps: warp-private, NO barriers ----
            #pragma unroll 1
            for (int tt = 0; tt < 64; tt++) {
                ull aI = bIv, aF = bFv, aZ = bZv, aO = bOv;
                const ull* __restrict__ xr = x2 + half * 4096 + (tbase + tt) * 8;
                #pragma unroll
                for (int d = 0; d < 8; d++) {
                    ull xv = xr[d];
                    aI = f2fma(xv, wIv[d], aI);
                    aF = f2fma(xv, wFv[d], aF);
                    aZ = f2fma(xv, wZv[d], aZ);
                    aO = f2fma(xv, wOv[d], aO);
                }
                #pragma unroll
                for (int d = 0; d < 15; d++) {
                    float hv0 = __shfl_sync(0xffffffffu, h0, srcbase + d);
                    float hv1 = __shfl_sync(0xffffffffu, h1, srcbase + d);
                    ull hv = f2pack(hv0, hv1);
                    aI = f2fma(hv, rIv[d], aI);
                    aF = f2fma(hv, rFv[d], aF);
                    aZ = f2fma(hv, rZv[d], aZ);
                    aO = f2fma(hv, rOv[d], aO);
                }
                float itx, ity, ftx, fty, ztx, zty, otx, oty;
                f2unpack(aI, itx, ity); f2unpack(aF, ftx, fty);
                f2unpack(aZ, ztx, zty); f2unpack(aO, otx, oty);
                h0 = cellf(itx, ftx, ztx, otx, c0, n0, m0);
                h1 = cellf(ity, fty, zty, oty, c1, n1, m1);
                if (act)
                    hsb[half * (64 * ST) + tt * ST + slot] = f2pack(h0, h1);
            }
            __syncthreads();
            // ---- projection: x[t] += hs[t] @ Wp^T + bp (chunk of 64 steps) ----
            {
                const int tl = tid & 63;
                const int bb = tid >> 6;
                ull acc[8];
                #pragma unroll
                for (int d = 0; d < 8; d++) acc[d] = 0ull;
                const ull* __restrict__ hsr = hsb + bb * (64 * ST) + tl * ST;
                #pragma unroll 4
                for (int p = 0; p < NPAIR; p++) {
                    ull hv = hsr[p];
                    #pragma unroll
                    for (int d = 0; d < 8; d++)
                        acc[d] = f2fma(hv, wp2[d * NPAIR + p], acc[d]);
                }
                ull* xw = x2 + bb * 4096 + (tbase + tl) * 8;
                #pragma unroll
                for (int d = 0; d < 8; d++) {
                    float ax, ay; f2unpack(acc[d], ax, ay);
                    float nv = f2lo(xw[d]) + ax + ay + bps[d];
                    xw[d] = f2pack(nv, nv);
                }
            }
            __syncthreads();
        }
    }

    // stash last timestep (layer-stack output) for the finalize kernel
    if (tid < 16) {
        int bbi = tid >> 3, d = tid & 7;
        g_last[(b0 + bbi) * D_ + d] = f2lo(x2[bbi * 4096 + 511 * 8 + d]);
    }
}

__global__ void finalize_kernel(const float* __restrict__ gamma,
                                const float* __restrict__ beta,
                                const float* __restrict__ wfc,
                                const float* __restrict__ bfc,
                                float* __restrict__ out)
{
    __shared__ float red[8][8];
    __shared__ float smu[8], svar[8];
    int b = threadIdx.x;
    int lane = b & 31, w = b >> 5;
    float v[8];
    #pragma unroll
    for (int d = 0; d < 8; d++) v[d] = g_last[b * 8 + d];

    #pragma unroll
    for (int d = 0; d < 8; d++) {
        float sv = v[d];
        #pragma unroll
        for (int o = 16; o > 0; o >>= 1) sv += __shfl_xor_sync(0xffffffffu, sv, o);
        if (lane == 0) red[d][w] = sv;
    }
    __syncthreads();
    if (b < 8) {
        float sv = 0.f;
        #pragma unroll
        for (int k = 0; k < 8; k++) sv += red[b][k];
        smu[b] = sv * (1.f / 256.f);
    }
    __syncthreads();
    float mu[8];
    #pragma unroll
    for (int d = 0; d < 8; d++) mu[d] = smu[d];
    __syncthreads();

    #pragma unroll
    for (int d = 0; d < 8; d++) {
        float dv = v[d] - mu[d];
        float sv = dv * dv;
        #pragma unroll
        for (int o = 16; o > 0; o >>= 1) sv += __shfl_xor_sync(0xffffffffu, sv, o);
        if (lane == 0) red[d][w] = sv;
    }
    __syncthreads();
    if (b < 8) {
        float sv = 0.f;
        #pragma unroll
        for (int k = 0; k < 8; k++) sv += red[b][k];
        svar[b] = sv * (1.f / 256.f);
    }
    __syncthreads();

    float acc = bfc[0];
    #pragma unroll
    for (int d = 0; d < 8; d++) {
        float bn = (v[d] - mu[d]) * rsqrtf(svar[d] + 1e-5f) * gamma[d] + beta[d];
        acc = fmaf(bn, wfc[d], acc);
    }
    out[b] = 1.f / (1.f + expf(-acc));
}

extern "C" void kernel_launch(void* const* d_in, const int* in_sizes, int n_in,
                              void* d_out, int out_size) {
    const float* X    = (const float*)d_in[0];
    const float* Wi   = (const float*)d_in[1];
    const float* Wf   = (const float*)d_in[2];
    const float* Wz   = (const float*)d_in[3];
    const float* Wo   = (const float*)d_in[4];
    const float* Ri   = (const float*)d_in[5];
    const float* Rf   = (const float*)d_in[6];
    const float* Rz   = (const float*)d_in[7];
    const float* Ro   = (const float*)d_in[8];
    const float* bi   = (const float*)d_in[9];
    const float* bf   = (const float*)d_in[10];
    const float* bz   = (const float*)d_in[11];
    const float* bo   = (const float*)d_in[12];
    const float* Wp   = (const float*)d_in[13];
    const float* bp   = (const float*)d_in[14];
    const float* gam  = (const float*)d_in[15];
    const float* bet  = (const float*)d_in[16];
    const float* Wfc  = (const float*)d_in[17];
    const float* bfc  = (const float*)d_in[18];

    cudaFuncSetAttribute(slstm_kernel,
                         cudaFuncAttributeMaxDynamicSharedMemorySize, SMEM_BYTES);
    slstm_kernel<<<128, 128, SMEM_BYTES>>>(X, Wi, Wf, Wz, Wo, Ri, Rf, Rz, Ro,
                                           bi, bf, bz, bo, Wp, bp);
    finalize_kernel<<<1, 256>>>(gam, bet, Wfc, bfc, (float*)d_out);
}